// round 9
// baseline (speedup 1.0000x reference)
#include <cuda_runtime.h>
#include <cuda_fp16.h>
#include <cstdint>

#define N_NODES 50000
#define D_FEAT  128
#define N_EDGES 800000
#define CAP     64          // per-row bucket capacity (max observed degree ~40)
#define OVF_CAP 4096

// Scratch (device globals; no allocation allowed)
__device__ __half             g_xh[(size_t)N_NODES * D_FEAT];     // 12.8 MB: fp16 tangent
__device__ unsigned long long g_bucket[(size_t)N_NODES * CAP];    // (col<<32)|val_bits
__device__ int                g_cnt[N_NODES];
__device__ int                g_ovf_cnt;
__device__ uint4              g_ovf[OVF_CAP];                     // {row, col, val_bits, _}

// ---------------------------------------------------------------------------
// Kernel A: logmap0 factor + fp16 tangent convert + zero counters.
// EXACT R8 version.
// ---------------------------------------------------------------------------
__global__ __launch_bounds__(256) void factor_kernel(const float* __restrict__ x) {
    const int warp_id = (blockIdx.x * blockDim.x + threadIdx.x) >> 5;
    const int lane    = threadIdx.x & 31;
    const int l       = lane & 7;
    const int row     = warp_id * 4 + (lane >> 3);

    int t = blockIdx.x * blockDim.x + threadIdx.x;
    if (t < N_NODES) g_cnt[t] = 0;
    if (t == 0) g_ovf_cnt = 0;

    if (row >= N_NODES) return;

    const float4* xr = reinterpret_cast<const float4*>(x) + (size_t)row * 32;
    float4 v[4];
    #pragma unroll
    for (int k = 0; k < 4; k++) v[k] = xr[l + 8 * k];

    float ss = 0.f;
    #pragma unroll
    for (int k = 0; k < 4; k++)
        ss += v[k].x * v[k].x + v[k].y * v[k].y + v[k].z * v[k].z + v[k].w * v[k].w;
    ss += __shfl_xor_sync(0xFFFFFFFFu, ss, 1);
    ss += __shfl_xor_sync(0xFFFFFFFFu, ss, 2);
    ss += __shfl_xor_sync(0xFFFFFFFFu, ss, 4);

    float norm = fmaxf(sqrtf(ss), 1e-15f);
    float u = fminf(norm, 0.99999988f);          // artanh clamp (inactive: ||x|| ~ 0.01)
    float factor = atanhf(u) / norm;

    uint2* xh = reinterpret_cast<uint2*>(g_xh + (size_t)row * D_FEAT);
    #pragma unroll
    for (int k = 0; k < 4; k++) {
        __half2 lo = __floats2half2_rn(v[k].x * factor, v[k].y * factor);
        __half2 hi = __floats2half2_rn(v[k].z * factor, v[k].w * factor);
        uint2 packed;
        packed.x = *reinterpret_cast<unsigned*>(&lo);
        packed.y = *reinterpret_cast<unsigned*>(&hi);
        xh[l + 8 * k] = packed;
    }
}

// ---------------------------------------------------------------------------
// Kernel B: bucket edges by destination row. EXACT R8 version.
// ---------------------------------------------------------------------------
__global__ __launch_bounds__(256) void scatter_kernel(
    const int* __restrict__ adj_rows,
    const int* __restrict__ adj_cols,
    const float* __restrict__ adj_vals)
{
    int e = blockIdx.x * blockDim.x + threadIdx.x;
    if (e >= N_EDGES) return;
    int   r = adj_rows[e];
    int   c = adj_cols[e];
    float s = adj_vals[e];

    int pos = atomicAdd(&g_cnt[r], 1);
    if (pos < CAP) {
        g_bucket[(size_t)r * CAP + pos] =
            ((unsigned long long)(unsigned)c << 32) | (unsigned)__float_as_uint(s);
    } else {
        int o = atomicAdd(&g_ovf_cnt, 1);
        if (o < OVF_CAP) g_ovf[o] = make_uint4((unsigned)r, (unsigned)c, __float_as_uint(s), 0u);
    }
}

// ---------------------------------------------------------------------------
// Kernel C: aggregate — ONE CHANGE: 4 independent gathers in flight per thread
// (8 edges per warp-iteration), loads batched before converts.
// Half-warp layout as R8: lanes 0-15 even edges, 16-31 odd edges; uint4/lane.
// ---------------------------------------------------------------------------
__global__ __launch_bounds__(256) void aggregate_kernel(float* __restrict__ out) {
    int gw   = (blockIdx.x * blockDim.x + threadIdx.x) >> 5;
    int lane = threadIdx.x & 31;
    if (gw >= N_NODES) return;

    const int half = lane >> 4;          // 0: even edges, 1: odd edges
    const int hl   = lane & 15;          // feature chunk within half

    int raw_n = g_cnt[gw];
    int n = (raw_n < CAP) ? raw_n : CAP;
    const unsigned long long* bk = g_bucket + (size_t)gw * CAP;
    const uint4* xh4 = reinterpret_cast<const uint4*>(g_xh);

    float acc[8] = {0.f, 0.f, 0.f, 0.f, 0.f, 0.f, 0.f, 0.f};

    int e = 0;
    // main loop: 8 edges per iteration, 4 independent row-gathers per thread
    for (; e + 8 <= n; e += 8) {
        unsigned long long p0 = bk[e     + half];
        unsigned long long p1 = bk[e + 2 + half];
        unsigned long long p2 = bk[e + 4 + half];
        unsigned long long p3 = bk[e + 6 + half];
        uint4 q0 = xh4[((p0 >> 32) << 4) + hl];
        uint4 q1 = xh4[((p1 >> 32) << 4) + hl];
        uint4 q2 = xh4[((p2 >> 32) << 4) + hl];
        uint4 q3 = xh4[((p3 >> 32) << 4) + hl];
        float s0 = __uint_as_float((unsigned)p0);
        float s1 = __uint_as_float((unsigned)p1);
        float s2 = __uint_as_float((unsigned)p2);
        float s3 = __uint_as_float((unsigned)p3);
        #pragma unroll
        for (int j = 0; j < 4; j++) {
            unsigned w0 = (&q0.x)[j], w1 = (&q1.x)[j], w2 = (&q2.x)[j], w3 = (&q3.x)[j];
            float2 f0 = __half22float2(*reinterpret_cast<__half2*>(&w0));
            float2 f1 = __half22float2(*reinterpret_cast<__half2*>(&w1));
            float2 f2 = __half22float2(*reinterpret_cast<__half2*>(&w2));
            float2 f3 = __half22float2(*reinterpret_cast<__half2*>(&w3));
            acc[2*j]   += s0 * f0.x + s1 * f1.x + s2 * f2.x + s3 * f3.x;
            acc[2*j+1] += s0 * f0.y + s1 * f1.y + s2 * f2.y + s3 * f3.y;
        }
    }
    // tail: 2 edges per iteration
    for (; e + 2 <= n; e += 2) {
        unsigned long long p = bk[e + half];
        uint4 q = xh4[((p >> 32) << 4) + hl];
        float s = __uint_as_float((unsigned)p);
        #pragma unroll
        for (int j = 0; j < 4; j++) {
            unsigned w = (&q.x)[j];
            float2 f = __half22float2(*reinterpret_cast<__half2*>(&w));
            acc[2*j]   += s * f.x;
            acc[2*j+1] += s * f.y;
        }
    }
    // odd leftover: lower half only
    if (e < n && half == 0) {
        unsigned long long p = bk[e];
        uint4 q = xh4[((p >> 32) << 4) + hl];
        float s = __uint_as_float((unsigned)p);
        #pragma unroll
        for (int j = 0; j < 4; j++) {
            unsigned w = (&q.x)[j];
            float2 f = __half22float2(*reinterpret_cast<__half2*>(&w));
            acc[2*j]   += s * f.x;
            acc[2*j+1] += s * f.y;
        }
    }

    // Overflow fixup (rare; raw_n <= CAP on this dataset)
    if (raw_n > CAP && half == 0) {
        int ovf_n = g_ovf_cnt;
        ovf_n = (ovf_n < OVF_CAP) ? ovf_n : OVF_CAP;
        for (int i = 0; i < ovf_n; i++) {
            uint4 qo = g_ovf[i];
            if ((int)qo.x == gw) {
                uint4 q = xh4[((size_t)qo.y << 4) + hl];
                float s = __uint_as_float(qo.z);
                #pragma unroll
                for (int j = 0; j < 4; j++) {
                    unsigned w = (&q.x)[j];
                    float2 f = __half22float2(*reinterpret_cast<__half2*>(&w));
                    acc[2*j]   += s * f.x;
                    acc[2*j+1] += s * f.y;
                }
            }
        }
    }

    // combine even/odd halves
    #pragma unroll
    for (int i = 0; i < 8; i++)
        acc[i] += __shfl_xor_sync(0xFFFFFFFFu, acc[i], 16);

    if (half == 0) {
        float4* o4 = reinterpret_cast<float4*>(out) + (size_t)gw * 32 + hl * 2;
        o4[0] = make_float4(acc[0], acc[1], acc[2], acc[3]);
        o4[1] = make_float4(acc[4], acc[5], acc[6], acc[7]);
    }
}

// ---------------------------------------------------------------------------
// Launch sequence: EXACT R8 (factor/zero -> scatter -> aggregate, 3 kernels)
// ---------------------------------------------------------------------------
extern "C" void kernel_launch(void* const* d_in, const int* in_sizes, int n_in,
                              void* d_out, int out_size) {
    const float* x        = (const float*)d_in[0];
    const int*   adj_rows = (const int*)  d_in[1];
    const int*   adj_cols = (const int*)  d_in[2];
    const float* adj_vals = (const float*)d_in[3];
    float*       out      = (float*)      d_out;

    {
        int blocks = (N_NODES + 31) / 32;
        factor_kernel<<<blocks, 256>>>(x);
    }
    scatter_kernel<<<(N_EDGES + 255) / 256, 256>>>(adj_rows, adj_cols, adj_vals);
    {
        int blocks = (N_NODES * 32 + 255) / 256;
        aggregate_kernel<<<blocks, 256>>>(out);
    }
}